// round 13
// baseline (speedup 1.0000x reference)
#include <cuda_runtime.h>
#include <cuda_bf16.h>
#include <cstdint>

#define N_NODES 50000
#define E_EDGES 800000
#define F_IN    128
#define F_OUT   64

// Scratch: support = (X @ W) * t  -- 12.8 MB static.
__device__ float g_support[N_NODES * F_OUT];

// ===========================================================================
// Kernel 1: GEMM via mma.sync. A loaded gmem->regs (bf16 hi/lo split in regs),
// B = W^T hi/lo split in-kernel into smem + ldmatrix. M=128/CTA, 8 warps.
// Bias-init of `out` folded into the tail.
// ===========================================================================
#define GT 256
#define ASTR 272                       // padded smem row stride (bytes)
#define SM_BHI 0
#define SM_BLO (SM_BHI + 64 * ASTR)    // 17408
#define SM_TOTAL (SM_BLO + 64 * ASTR)  // 34816

__device__ __forceinline__ uint32_t smem_u32(const void* p) {
    uint32_t a;
    asm("{ .reg .u64 tmp; cvta.to.shared.u64 tmp, %1; cvt.u32.u64 %0, tmp; }"
        : "=r"(a) : "l"(p));
    return a;
}

__device__ __forceinline__ void ldmatrix_x4(uint32_t* r, uint32_t addr) {
    asm volatile("ldmatrix.sync.aligned.m8n8.x4.shared.b16 {%0,%1,%2,%3}, [%4];"
                 : "=r"(r[0]), "=r"(r[1]), "=r"(r[2]), "=r"(r[3]) : "r"(addr));
}

__device__ __forceinline__ void mma_bf16(float* d, const uint32_t* a,
                                         const uint32_t* b) {
    asm volatile(
        "mma.sync.aligned.m16n8k16.row.col.f32.bf16.bf16.f32 "
        "{%0,%1,%2,%3}, {%4,%5,%6,%7}, {%8,%9}, {%0,%1,%2,%3};"
        : "+f"(d[0]), "+f"(d[1]), "+f"(d[2]), "+f"(d[3])
        : "r"(a[0]), "r"(a[1]), "r"(a[2]), "r"(a[3]), "r"(b[0]), "r"(b[1]));
}

__device__ __forceinline__ uint32_t pack_hi(float2 v) {
    __nv_bfloat162 h = __floats2bfloat162_rn(v.x, v.y);
    return *(uint32_t*)&h;
}
__device__ __forceinline__ uint32_t pack_lo(float2 v) {
    __nv_bfloat162 h = __floats2bfloat162_rn(v.x, v.y);
    float rx = v.x - __bfloat162float(__low2bfloat16(h));
    float ry = v.y - __bfloat162float(__high2bfloat16(h));
    __nv_bfloat162 l = __floats2bfloat162_rn(rx, ry);
    return *(uint32_t*)&l;
}

__global__ void __launch_bounds__(GT, 3)
gemm_tc_kernel(const float* __restrict__ x,
               const float* __restrict__ t,
               const float* __restrict__ weight,
               const float* __restrict__ bias,
               float* __restrict__ out)
{
    extern __shared__ char smem[];
    const uint32_t sb = smem_u32(smem);
    const int tid  = threadIdx.x;
    const int wid  = tid >> 5;
    const int lane = tid & 31;
    const int row0 = blockIdx.x * 128;

    // ---- stage B = W^T hi/lo split in-kernel (weight is L2-hot, 32KB)
    for (int i = tid; i < F_IN * F_OUT; i += GT) {
        int f = i & 63;
        int k = i >> 6;
        float v = __ldg(&weight[i]);
        __nv_bfloat16 h = __float2bfloat16(v);
        __nv_bfloat16 l = __float2bfloat16(v - __bfloat162float(h));
        *(__nv_bfloat16*)(smem + SM_BHI + f * ASTR + k * 2) = h;
        *(__nv_bfloat16*)(smem + SM_BLO + f * ASTR + k * 2) = l;
    }
    __syncthreads();

    // ---- A: direct gmem float2 loads in mma fragment layout
    const int g   = lane >> 2;
    const int tig = lane & 3;
    const int r0g = row0 + wid * 16 + g;
    const int r1g = r0g + 8;
    const bool v0 = r0g < N_NODES;
    const bool v1 = r1g < N_NODES;
    const float2* p0 = (const float2*)&x[(size_t)r0g * F_IN];
    const float2* p1 = (const float2*)&x[(size_t)r1g * F_IN];
    const float2 z2 = make_float2(0.f, 0.f);

    float acc[8][4];
    #pragma unroll
    for (int j = 0; j < 8; j++)
        #pragma unroll
        for (int q = 0; q < 4; q++)
            acc[j][q] = 0.0f;

    const int afrag = lane >> 3;
    const int arow  = lane & 7;

    float2 c00 = v0 ? p0[tig]     : z2;
    float2 c10 = v1 ? p1[tig]     : z2;
    float2 c01 = v0 ? p0[tig + 4] : z2;
    float2 c11 = v1 ? p1[tig + 4] : z2;

    #pragma unroll
    for (int kk = 0; kk < 8; kk++) {
        float2 n00, n10, n01, n11;
        if (kk < 7) {
            int o = (kk + 1) * 8 + tig;
            n00 = v0 ? p0[o]     : z2;
            n10 = v1 ? p1[o]     : z2;
            n01 = v0 ? p0[o + 4] : z2;
            n11 = v1 ? p1[o + 4] : z2;
        }

        uint32_t ahi[4], alo[4];
        ahi[0] = pack_hi(c00); alo[0] = pack_lo(c00);
        ahi[1] = pack_hi(c10); alo[1] = pack_lo(c10);
        ahi[2] = pack_hi(c01); alo[2] = pack_lo(c01);
        ahi[3] = pack_hi(c11); alo[3] = pack_lo(c11);

        #pragma unroll
        for (int j2 = 0; j2 < 4; j2++) {
            uint32_t b_off = (uint32_t)((j2 * 16 + (afrag >> 1) * 8 + arow) * ASTR
                                        + (kk * 16 + (afrag & 1) * 8) * 2);
            uint32_t bhi[4], blo[4];
            ldmatrix_x4(bhi, sb + SM_BHI + b_off);
            ldmatrix_x4(blo, sb + SM_BLO + b_off);

            mma_bf16(acc[j2 * 2 + 0], ahi, bhi + 0);
            mma_bf16(acc[j2 * 2 + 1], ahi, bhi + 2);
            mma_bf16(acc[j2 * 2 + 0], ahi, blo + 0);
            mma_bf16(acc[j2 * 2 + 1], ahi, blo + 2);
            mma_bf16(acc[j2 * 2 + 0], alo, bhi + 0);
            mma_bf16(acc[j2 * 2 + 1], alo, bhi + 2);
        }

        c00 = n00; c10 = n10; c01 = n01; c11 = n11;
    }

    // ---- epilogue: scale by t, store support
    int r0 = row0 + wid * 16 + (lane >> 2);
    int c0 = (lane & 3) * 2;
    float tv0 = 0.f, tv1 = 0.f;
    if (r0 < N_NODES)     tv0 = __ldg(&t[r0]);
    if (r0 + 8 < N_NODES) tv1 = __ldg(&t[r0 + 8]);

    #pragma unroll
    for (int j = 0; j < 8; j++) {
        if (r0 < N_NODES) {
            float2 v = make_float2(acc[j][0] * tv0, acc[j][1] * tv0);
            *(float2*)&g_support[(size_t)r0 * F_OUT + j * 8 + c0] = v;
        }
        if (r0 + 8 < N_NODES) {
            float2 v = make_float2(acc[j][2] * tv1, acc[j][3] * tv1);
            *(float2*)&g_support[(size_t)(r0 + 8) * F_OUT + j * 8 + c0] = v;
        }
    }

    // ---- folded bias init: out[n][f] = bias[f]  (grid-stride float4)
    {
        const int total4 = N_NODES * F_OUT / 4;            // 800000
        const int stride = gridDim.x * GT;
        float4* out4 = (float4*)out;
        float4 b0 = *(const float4*)&bias[(tid & 15) * 4];
        for (int i = blockIdx.x * GT + tid; i < total4; i += stride)
            out4[i] = b0;
    }
}

// ---------------------------------------------------------------------------
// Kernel 2: scatter-add.  16 threads per edge, one float4 each.
// out[dst[e]][:] += support[src[e]][:] * edge_vals[e]
// ---------------------------------------------------------------------------
__device__ __forceinline__ void red_add_v4(float* addr, float a, float b,
                                           float c, float d)
{
    asm volatile("red.global.add.v4.f32 [%0], {%1, %2, %3, %4};"
                 :: "l"(addr), "f"(a), "f"(b), "f"(c), "f"(d)
                 : "memory");
}

__global__ void __launch_bounds__(256)
scatter_kernel(const int* __restrict__ src,
               const int* __restrict__ dst,
               const float* __restrict__ edge_vals,
               float* __restrict__ out)
{
    int gid = blockIdx.x * blockDim.x + threadIdx.x;
    int e = gid >> 4;
    int c = gid & 15;
    if (e >= E_EDGES) return;

    int s = __ldg(&src[e]);
    int d = __ldg(&dst[e]);
    float ev = __ldg(&edge_vals[e]);

    const float4* sp = (const float4*)&g_support[(size_t)s * F_OUT] + c;
    float4 v = __ldg(sp);

    red_add_v4(&out[(size_t)d * F_OUT + c * 4],
               v.x * ev, v.y * ev, v.z * ev, v.w * ev);
}

// ---------------------------------------------------------------------------
// Launch.  Inputs (metadata order): x, t, src, dst, edge_vals, weight, bias
// ---------------------------------------------------------------------------
extern "C" void kernel_launch(void* const* d_in, const int* in_sizes, int n_in,
                              void* d_out, int out_size)
{
    const float* x         = (const float*)d_in[0];
    const float* t         = (const float*)d_in[1];
    const int*   src       = (const int*)d_in[2];
    const int*   dst       = (const int*)d_in[3];
    const float* edge_vals = (const float*)d_in[4];
    const float* weight    = (const float*)d_in[5];
    const float* bias      = (const float*)d_in[6];
    float*       out       = (float*)d_out;

    cudaFuncSetAttribute(gemm_tc_kernel,
                         cudaFuncAttributeMaxDynamicSharedMemorySize, SM_TOTAL);

    // 1. support = (X @ W) * t  + bias-init of out (folded)
    int gemm_blocks = (N_NODES + 127) / 128;            // 391
    gemm_tc_kernel<<<gemm_blocks, GT, SM_TOTAL>>>(x, t, weight, bias, out);

    // 2. scatter-add over edges
    long long sthreads = (long long)E_EDGES * 16;
    int sblocks = (int)((sthreads + 255) / 256);        // 50000
    scatter_kernel<<<sblocks, 256>>>(src, dst, edge_vals, out);
}

// round 14
// speedup vs baseline: 1.5991x; 1.5991x over previous
#include <cuda_runtime.h>
#include <cuda_bf16.h>
#include <cstdint>

#define N_NODES 50000
#define E_EDGES 800000
#define F_IN    128
#define F_OUT   64

// Scratch: support = (X @ W) * t  -- 12.8 MB static.
__device__ float g_support[N_NODES * F_OUT];

// ===========================================================================
// Kernel 1: GEMM via mma.sync. A loaded gmem->regs (bf16 hi/lo split in regs),
// B = W^T hi/lo split in-kernel into smem + ldmatrix. M=128/CTA, 8 warps.
// Bias-init of `out` folded into the tail.
// ===========================================================================
#define GT 256
#define ASTR 272                       // padded smem row stride (bytes)
#define SM_BHI 0
#define SM_BLO (SM_BHI + 64 * ASTR)    // 17408
#define SM_TOTAL (SM_BLO + 64 * ASTR)  // 34816

__device__ __forceinline__ uint32_t smem_u32(const void* p) {
    uint32_t a;
    asm("{ .reg .u64 tmp; cvta.to.shared.u64 tmp, %1; cvt.u32.u64 %0, tmp; }"
        : "=r"(a) : "l"(p));
    return a;
}

__device__ __forceinline__ void ldmatrix_x4(uint32_t* r, uint32_t addr) {
    asm volatile("ldmatrix.sync.aligned.m8n8.x4.shared.b16 {%0,%1,%2,%3}, [%4];"
                 : "=r"(r[0]), "=r"(r[1]), "=r"(r[2]), "=r"(r[3]) : "r"(addr));
}

__device__ __forceinline__ void mma_bf16(float* d, const uint32_t* a,
                                         const uint32_t* b) {
    asm volatile(
        "mma.sync.aligned.m16n8k16.row.col.f32.bf16.bf16.f32 "
        "{%0,%1,%2,%3}, {%4,%5,%6,%7}, {%8,%9}, {%0,%1,%2,%3};"
        : "+f"(d[0]), "+f"(d[1]), "+f"(d[2]), "+f"(d[3])
        : "r"(a[0]), "r"(a[1]), "r"(a[2]), "r"(a[3]), "r"(b[0]), "r"(b[1]));
}

__device__ __forceinline__ uint32_t pack_hi(float2 v) {
    __nv_bfloat162 h = __floats2bfloat162_rn(v.x, v.y);
    return *(uint32_t*)&h;
}
__device__ __forceinline__ uint32_t pack_lo(float2 v) {
    __nv_bfloat162 h = __floats2bfloat162_rn(v.x, v.y);
    float rx = v.x - __bfloat162float(__low2bfloat16(h));
    float ry = v.y - __bfloat162float(__high2bfloat16(h));
    __nv_bfloat162 l = __floats2bfloat162_rn(rx, ry);
    return *(uint32_t*)&l;
}

__global__ void __launch_bounds__(GT, 3)
gemm_tc_kernel(const float* __restrict__ x,
               const float* __restrict__ t,
               const float* __restrict__ weight,
               const float* __restrict__ bias,
               float* __restrict__ out)
{
    extern __shared__ char smem[];
    const uint32_t sb = smem_u32(smem);
    const int tid  = threadIdx.x;
    const int wid  = tid >> 5;
    const int lane = tid & 31;
    const int row0 = blockIdx.x * 128;

    // ---- stage B = W^T hi/lo split in-kernel (weight is L2-hot, 32KB)
    for (int i = tid; i < F_IN * F_OUT; i += GT) {
        int f = i & 63;
        int k = i >> 6;
        float v = __ldg(&weight[i]);
        __nv_bfloat16 h = __float2bfloat16(v);
        __nv_bfloat16 l = __float2bfloat16(v - __bfloat162float(h));
        *(__nv_bfloat16*)(smem + SM_BHI + f * ASTR + k * 2) = h;
        *(__nv_bfloat16*)(smem + SM_BLO + f * ASTR + k * 2) = l;
    }
    __syncthreads();

    // ---- A: direct gmem float2 loads in mma fragment layout
    const int g   = lane >> 2;
    const int tig = lane & 3;
    const int r0g = row0 + wid * 16 + g;
    const int r1g = r0g + 8;
    const bool v0 = r0g < N_NODES;
    const bool v1 = r1g < N_NODES;
    const float2* p0 = (const float2*)&x[(size_t)r0g * F_IN];
    const float2* p1 = (const float2*)&x[(size_t)r1g * F_IN];
    const float2 z2 = make_float2(0.f, 0.f);

    float acc[8][4];
    #pragma unroll
    for (int j = 0; j < 8; j++)
        #pragma unroll
        for (int q = 0; q < 4; q++)
            acc[j][q] = 0.0f;

    const int afrag = lane >> 3;
    const int arow  = lane & 7;

    float2 c00 = v0 ? p0[tig]     : z2;
    float2 c10 = v1 ? p1[tig]     : z2;
    float2 c01 = v0 ? p0[tig + 4] : z2;
    float2 c11 = v1 ? p1[tig + 4] : z2;

    #pragma unroll
    for (int kk = 0; kk < 8; kk++) {
        float2 n00, n10, n01, n11;
        if (kk < 7) {
            int o = (kk + 1) * 8 + tig;
            n00 = v0 ? p0[o]     : z2;
            n10 = v1 ? p1[o]     : z2;
            n01 = v0 ? p0[o + 4] : z2;
            n11 = v1 ? p1[o + 4] : z2;
        }

        uint32_t ahi[4], alo[4];
        ahi[0] = pack_hi(c00); alo[0] = pack_lo(c00);
        ahi[1] = pack_hi(c10); alo[1] = pack_lo(c10);
        ahi[2] = pack_hi(c01); alo[2] = pack_lo(c01);
        ahi[3] = pack_hi(c11); alo[3] = pack_lo(c11);

        #pragma unroll
        for (int j2 = 0; j2 < 4; j2++) {
            uint32_t b_off = (uint32_t)((j2 * 16 + (afrag >> 1) * 8 + arow) * ASTR
                                        + (kk * 16 + (afrag & 1) * 8) * 2);
            uint32_t bhi[4], blo[4];
            ldmatrix_x4(bhi, sb + SM_BHI + b_off);
            ldmatrix_x4(blo, sb + SM_BLO + b_off);

            mma_bf16(acc[j2 * 2 + 0], ahi, bhi + 0);
            mma_bf16(acc[j2 * 2 + 1], ahi, bhi + 2);
            mma_bf16(acc[j2 * 2 + 0], ahi, blo + 0);
            mma_bf16(acc[j2 * 2 + 1], ahi, blo + 2);
            mma_bf16(acc[j2 * 2 + 0], alo, bhi + 0);
            mma_bf16(acc[j2 * 2 + 1], alo, bhi + 2);
        }

        c00 = n00; c10 = n10; c01 = n01; c11 = n11;
    }

    // ---- epilogue: scale by t, store support
    int r0 = row0 + wid * 16 + (lane >> 2);
    int c0 = (lane & 3) * 2;
    float tv0 = 0.f, tv1 = 0.f;
    if (r0 < N_NODES)     tv0 = __ldg(&t[r0]);
    if (r0 + 8 < N_NODES) tv1 = __ldg(&t[r0 + 8]);

    #pragma unroll
    for (int j = 0; j < 8; j++) {
        if (r0 < N_NODES) {
            float2 v = make_float2(acc[j][0] * tv0, acc[j][1] * tv0);
            *(float2*)&g_support[(size_t)r0 * F_OUT + j * 8 + c0] = v;
        }
        if (r0 + 8 < N_NODES) {
            float2 v = make_float2(acc[j][2] * tv1, acc[j][3] * tv1);
            *(float2*)&g_support[(size_t)(r0 + 8) * F_OUT + j * 8 + c0] = v;
        }
    }

    // ---- folded bias init: out[n][f] = bias[f]  (grid-stride float4)
    {
        const int total4 = N_NODES * F_OUT / 4;            // 800000
        const int stride = gridDim.x * GT;
        float4* out4 = (float4*)out;
        float4 b0 = *(const float4*)&bias[(tid & 15) * 4];
        for (int i = blockIdx.x * GT + tid; i < total4; i += stride)
            out4[i] = b0;
    }
}

// ---------------------------------------------------------------------------
// Kernel 2: scatter-add.  8 threads per EDGE-PAIR: thread handles one float4
// chunk (c = tid&15 -> chunk c/2? no: c = gid&7 doubled) for 2 edges.
// Index/value loads amortized over 2 edges; 2 independent LDG.128 in flight.
// ---------------------------------------------------------------------------
__device__ __forceinline__ void red_add_v4(float* addr, float a, float b,
                                           float c, float d)
{
    asm volatile("red.global.add.v4.f32 [%0], {%1, %2, %3, %4};"
                 :: "l"(addr), "f"(a), "f"(b), "f"(c), "f"(d)
                 : "memory");
}

__global__ void __launch_bounds__(256)
scatter_kernel(const int* __restrict__ src,
               const int* __restrict__ dst,
               const float* __restrict__ edge_vals,
               float* __restrict__ out)
{
    // gid layout: 16 threads cover an edge PAIR (e0 = pair*2, e1 = pair*2+1).
    // Within the 16: c = gid & 15 indexes the float4 chunk; each thread
    // handles chunk c for BOTH edges.
    int gid  = blockIdx.x * blockDim.x + threadIdx.x;
    int pair = gid >> 4;
    int c    = gid & 15;
    int e0   = pair * 2;
    int e1   = e0 + 1;
    if (e0 >= E_EDGES) return;

    int   s0 = __ldg(&src[e0]);
    int   d0 = __ldg(&dst[e0]);
    float v0 = __ldg(&edge_vals[e0]);

    bool has1 = (e1 < E_EDGES);
    int   s1 = has1 ? __ldg(&src[e1]) : 0;
    int   d1 = has1 ? __ldg(&dst[e1]) : 0;
    float v1 = has1 ? __ldg(&edge_vals[e1]) : 0.0f;

    // two independent support loads -> MLP=2
    float4 a0 = __ldg((const float4*)&g_support[(size_t)s0 * F_OUT] + c);
    float4 a1 = has1 ? __ldg((const float4*)&g_support[(size_t)s1 * F_OUT] + c)
                     : make_float4(0.f, 0.f, 0.f, 0.f);

    red_add_v4(&out[(size_t)d0 * F_OUT + c * 4],
               a0.x * v0, a0.y * v0, a0.z * v0, a0.w * v0);
    if (has1)
        red_add_v4(&out[(size_t)d1 * F_OUT + c * 4],
                   a1.x * v1, a1.y * v1, a1.z * v1, a1.w * v1);
}

// ---------------------------------------------------------------------------
// Launch.  Inputs (metadata order): x, t, src, dst, edge_vals, weight, bias
// ---------------------------------------------------------------------------
extern "C" void kernel_launch(void* const* d_in, const int* in_sizes, int n_in,
                              void* d_out, int out_size)
{
    const float* x         = (const float*)d_in[0];
    const float* t         = (const float*)d_in[1];
    const int*   src       = (const int*)d_in[2];
    const int*   dst       = (const int*)d_in[3];
    const float* edge_vals = (const float*)d_in[4];
    const float* weight    = (const float*)d_in[5];
    const float* bias      = (const float*)d_in[6];
    float*       out       = (float*)d_out;

    cudaFuncSetAttribute(gemm_tc_kernel,
                         cudaFuncAttributeMaxDynamicSharedMemorySize, SM_TOTAL);

    // 1. support = (X @ W) * t  + bias-init of out (folded)
    int gemm_blocks = (N_NODES + 127) / 128;            // 391
    gemm_tc_kernel<<<gemm_blocks, GT, SM_TOTAL>>>(x, t, weight, bias, out);

    // 2. scatter-add over edges (8 threads/edge-pair * 2 edges)
    long long pairs    = (E_EDGES + 1) / 2;             // 400000
    long long sthreads = pairs * 16;
    int sblocks = (int)((sthreads + 255) / 256);        // 25000
    scatter_kernel<<<sblocks, 256>>>(src, dst, edge_vals, out);
}